// round 6
// baseline (speedup 1.0000x reference)
#include <cuda_runtime.h>
#include <math.h>

// Problem constants (fixed shapes: L=5, B=8, n=1024, d=64)
#define LNUM 5
#define BNUM 8
#define NLB  (LNUM * BNUM)       // 40
#define N    1024
#define D    64
#define S    8                   // n-dim splits per (l,b)
#define ROWS (N / S)             // 128 rows per chunk
#define TR   64                  // smem tile rows
#define GSZ  (D * D)             // 4096
#define STRIDE (3 * GSZ + 2 * D) // per-chunk scratch: XX, YY, XY, sx, sy

__device__ float g_part[NLB * S * STRIDE];   // ~15.9 MB scratch
__device__ float g_sums[NLB * 8 * 3];        // per (lb, slice): sXX, sYY, sXY

typedef unsigned long long u64;

// packed f32x2 FMA: acc.lo += a.lo*b.lo ; acc.hi += a.hi*b.hi
#define FMA2(acc, a, b) \
    asm("fma.rn.f32x2 %0, %1, %2, %0;" : "+l"(acc) : "l"(a), "l"(b))

static __device__ __forceinline__ u64 bcast2(float v) {
    u64 r;
    asm("mov.b64 %0, {%1, %1};" : "=l"(r) : "f"(v));
    return r;
}

static __device__ __forceinline__ float2 unpk2(u64 v) {
    float2 f;
    asm("mov.b64 {%0, %1}, %2;" : "=f"(f.x), "=f"(f.y) : "l"(v));
    return f;
}

// ---------------------------------------------------------------------------
// Kernel A: per (l,b,chunk,jhalf) partial Grams with packed FFMA2 and
// warp-uniform (broadcast) j-operands.
//   block = 128 threads = 4 warps. Warp w owns j-cols [32*jc + 8w, +8).
//   Lane l owns i-cols {2l, 2l+1}. Thread tile = 2i x 8j x 3 grams.
//   j-operand loads are warp-broadcast LDS.128 (1 crossbar phase).
// grid = NLB * S * 2 = 640 blocks.
// ---------------------------------------------------------------------------
__global__ void __launch_bounds__(128, 5) cka_partial_kernel(
    const float* __restrict__ X, const float* __restrict__ Y)
{
    __shared__ float Xs[TR * D];
    __shared__ float Ys[TR * D];
    __shared__ float red[128];

    const int tid = threadIdx.x;
    const int w = tid >> 5;         // warp 0..3
    const int l = tid & 31;         // lane
    const int bx = blockIdx.x;
    const int lb = bx >> 4;
    const int rem = bx & 15;
    const int chunk = rem >> 1;
    const int jc = rem & 1;

    const int jbase = 32 * jc + 8 * w;   // 8 j-cols per warp (uniform in warp)
    const int ibase = 2 * l;             // 2 i-cols per lane

    const float* xb = X + (size_t)lb * N * D + (size_t)chunk * ROWS * D;
    const float* yb = Y + (size_t)lb * N * D + (size_t)chunk * ROWS * D;

    // accumulators [i a][j pair p]; each u64 = 2 packed f32 j-lanes
    u64 aXX[2][4] = {};
    u64 aYY[2][4] = {};
    u64 aXY[2][4] = {};
    float csx = 0.f, csy = 0.f;
    const int col  = tid & 63;      // column-sum ownership
    const int half = tid >> 6;      // 2 row groups of 32

    #pragma unroll
    for (int t = 0; t < ROWS / TR; ++t) {
        __syncthreads();   // protect smem from previous iteration's readers
        const float4* xs4 = (const float4*)(xb + t * TR * D);
        const float4* ys4 = (const float4*)(yb + t * TR * D);
        float4* Xs4 = (float4*)Xs;
        float4* Ys4 = (float4*)Ys;
        #pragma unroll
        for (int k = 0; k < (TR * D / 4) / 128; ++k) {
            Xs4[tid + 128 * k] = xs4[tid + 128 * k];
            Ys4[tid + 128 * k] = ys4[tid + 128 * k];
        }
        __syncthreads();

        #pragma unroll 8
        for (int r = 0; r < TR; ++r) {
            const float* rowX = Xs + r * D;
            const float* rowY = Ys + r * D;
            // j operands: warp-uniform broadcast LDS.128 -> packed f32 pairs
            double2 xjA = *(const double2*)(rowX + jbase);       // pairs 0,1
            double2 xjB = *(const double2*)(rowX + jbase + 4);   // pairs 2,3
            double2 yjA = *(const double2*)(rowY + jbase);
            double2 yjB = *(const double2*)(rowY + jbase + 4);
            u64 xj[4] = {__double_as_longlong(xjA.x), __double_as_longlong(xjA.y),
                         __double_as_longlong(xjB.x), __double_as_longlong(xjB.y)};
            u64 yj[4] = {__double_as_longlong(yjA.x), __double_as_longlong(yjA.y),
                         __double_as_longlong(yjB.x), __double_as_longlong(yjB.y)};
            // i operands: lane-varying LDS.64
            float2 xi = *(const float2*)(rowX + ibase);
            float2 yi = *(const float2*)(rowY + ibase);
            u64 xb0 = bcast2(xi.x), xb1 = bcast2(xi.y);
            u64 yb0 = bcast2(yi.x), yb1 = bcast2(yi.y);
            #pragma unroll
            for (int p = 0; p < 4; ++p) {
                FMA2(aXX[0][p], xb0, xj[p]);
                FMA2(aXX[1][p], xb1, xj[p]);
                FMA2(aXY[0][p], xb0, yj[p]);
                FMA2(aXY[1][p], xb1, yj[p]);
                FMA2(aYY[0][p], yb0, yj[p]);
                FMA2(aYY[1][p], yb1, yj[p]);
            }
        }

        // column-sum partials (only jc==0 blocks; uniform branch)
        if (jc == 0) {
            #pragma unroll 8
            for (int rr = 0; rr < TR / 2; ++rr) {
                int r = half * (TR / 2) + rr;
                csx += Xs[r * D + col];
                csy += Ys[r * D + col];
            }
        }
    }

    float* out = g_part + (size_t)(lb * S + chunk) * STRIDE;

    if (jc == 0) {
        red[tid] = csx;
        __syncthreads();
        if (tid < 64) out[3 * GSZ + tid] = red[tid] + red[tid + 64];
        __syncthreads();
        red[tid] = csy;
        __syncthreads();
        if (tid < 64) out[3 * GSZ + 64 + tid] = red[tid] + red[tid + 64];
    }

    // epilogue: thread stores rows {2l, 2l+1}, cols [jbase, jbase+8)
    #pragma unroll
    for (int a = 0; a < 2; ++a) {
        int i = ibase + a;
        float* oXX = out + i * D + jbase;
        float* oYY = out + GSZ + i * D + jbase;
        float* oXY = out + 2 * GSZ + i * D + jbase;
        float2 p0, p1;
        p0 = unpk2(aXX[a][0]); p1 = unpk2(aXX[a][1]);
        *(float4*)oXX = {p0.x, p0.y, p1.x, p1.y};
        p0 = unpk2(aXX[a][2]); p1 = unpk2(aXX[a][3]);
        *(float4*)(oXX + 4) = {p0.x, p0.y, p1.x, p1.y};
        p0 = unpk2(aYY[a][0]); p1 = unpk2(aYY[a][1]);
        *(float4*)oYY = {p0.x, p0.y, p1.x, p1.y};
        p0 = unpk2(aYY[a][2]); p1 = unpk2(aYY[a][3]);
        *(float4*)(oYY + 4) = {p0.x, p0.y, p1.x, p1.y};
        p0 = unpk2(aXY[a][0]); p1 = unpk2(aXY[a][1]);
        *(float4*)oXY = {p0.x, p0.y, p1.x, p1.y};
        p0 = unpk2(aXY[a][2]); p1 = unpk2(aXY[a][3]);
        *(float4*)(oXY + 4) = {p0.x, p0.y, p1.x, p1.y};
    }
}

// ---------------------------------------------------------------------------
// Kernel B: per (lb, slice-of-8) reduce S chunk-partials, apply rank-1
// centering correction, partial Frobenius-square-reduce.
// grid = NLB * 8 = 320 blocks, 128 threads, float4 loads.
// ---------------------------------------------------------------------------
__global__ void __launch_bounds__(128) cka_reduce_kernel()
{
    const int lb = blockIdx.x >> 3;
    const int slice = blockIdx.x & 7;
    const int tid = threadIdx.x;
    __shared__ float sx[D], sy[D];
    __shared__ float red[128];

    const float* base = g_part + (size_t)lb * S * STRIDE;

    if (tid < 64) {
        float ax = 0.f, ay = 0.f;
        #pragma unroll
        for (int s = 0; s < S; ++s) {
            ax += base[s * STRIDE + 3 * GSZ + tid];
            ay += base[s * STRIDE + 3 * GSZ + 64 + tid];
        }
        sx[tid] = ax;
        sy[tid] = ay;
    }
    __syncthreads();

    const float inv_n = 1.0f / (float)N;
    const int f4i = slice * 128 + tid;   // float4 index within a 64x64 matrix
    const int i  = f4i >> 4;             // row
    const int jb = (f4i & 15) * 4;       // first column of the float4

    const float sxi = sx[i] * inv_n;
    const float syi = sy[i] * inv_n;
    const float4 sxj = *(const float4*)&sx[jb];
    const float4 syj = *(const float4*)&sy[jb];

    float4 gxx = {0,0,0,0}, gyy = {0,0,0,0}, gxy = {0,0,0,0};
    #pragma unroll
    for (int s = 0; s < S; ++s) {
        const float4* p = (const float4*)(base + (size_t)s * STRIDE);
        float4 v;
        v = p[f4i];
        gxx.x += v.x; gxx.y += v.y; gxx.z += v.z; gxx.w += v.w;
        v = p[1024 + f4i];
        gyy.x += v.x; gyy.y += v.y; gyy.z += v.z; gyy.w += v.w;
        v = p[2048 + f4i];
        gxy.x += v.x; gxy.y += v.y; gxy.z += v.z; gxy.w += v.w;
    }

    gxx.x -= sxi * sxj.x; gxx.y -= sxi * sxj.y; gxx.z -= sxi * sxj.z; gxx.w -= sxi * sxj.w;
    gyy.x -= syi * syj.x; gyy.y -= syi * syj.y; gyy.z -= syi * syj.z; gyy.w -= syi * syj.w;
    gxy.x -= sxi * syj.x; gxy.y -= sxi * syj.y; gxy.z -= sxi * syj.z; gxy.w -= sxi * syj.w;

    float vXX = gxx.x*gxx.x + gxx.y*gxx.y + gxx.z*gxx.z + gxx.w*gxx.w;
    float vYY = gyy.x*gyy.x + gyy.y*gyy.y + gyy.z*gyy.z + gyy.w*gyy.w;
    float vXY = gxy.x*gxy.x + gxy.y*gxy.y + gxy.z*gxy.z + gxy.w*gxy.w;

    float* gs = g_sums + (size_t)(lb * 8 + slice) * 3;

    red[tid] = vXX;
    __syncthreads();
    for (int off = 64; off > 0; off >>= 1) {
        if (tid < off) red[tid] += red[tid + off];
        __syncthreads();
    }
    if (tid == 0) gs[0] = red[0];
    __syncthreads();

    red[tid] = vYY;
    __syncthreads();
    for (int off = 64; off > 0; off >>= 1) {
        if (tid < off) red[tid] += red[tid + off];
        __syncthreads();
    }
    if (tid == 0) gs[1] = red[0];
    __syncthreads();

    red[tid] = vXY;
    __syncthreads();
    for (int off = 64; off > 0; off >>= 1) {
        if (tid < off) red[tid] += red[tid + off];
        __syncthreads();
    }
    if (tid == 0) gs[2] = red[0];
}

// ---------------------------------------------------------------------------
// Kernel C: final scalar loss = mean_l( -log( mean_b ratio + eps ) )
// ---------------------------------------------------------------------------
__global__ void cka_final_kernel(float* __restrict__ out)
{
    __shared__ float ratio[NLB];
    const int tid = threadIdx.x;
    if (tid < NLB) {
        float txx = 0.f, tyy = 0.f, txy = 0.f;
        #pragma unroll
        for (int s2 = 0; s2 < 8; ++s2) {
            const float* g = g_sums + (size_t)(tid * 8 + s2) * 3;
            txx += g[0];
            tyy += g[1];
            txy += g[2];
        }
        ratio[tid] = fabsf(txy) / (sqrtf(txx) * sqrtf(tyy));
    }
    __syncthreads();
    if (tid == 0) {
        float loss = 0.f;
        #pragma unroll
        for (int l = 0; l < LNUM; ++l) {
            float m = 0.f;
            #pragma unroll
            for (int b = 0; b < BNUM; ++b)
                m += ratio[l * BNUM + b];
            m *= (1.0f / (float)BNUM);
            loss += -logf(m + 1e-8f);
        }
        out[0] = loss * (1.0f / (float)LNUM);
    }
}

extern "C" void kernel_launch(void* const* d_in, const int* in_sizes, int n_in,
                              void* d_out, int out_size)
{
    const float* teacher = (const float*)d_in[0];
    const float* student = (const float*)d_in[1];
    float* out = (float*)d_out;

    cka_partial_kernel<<<NLB * S * 2, 128>>>(teacher, student);
    cka_reduce_kernel<<<NLB * 8, 128>>>();
    cka_final_kernel<<<1, 64>>>(out);
}